// round 4
// baseline (speedup 1.0000x reference)
#include <cuda_runtime.h>
#include <cuda_bf16.h>
#include <math.h>

// ---------------------------------------------------------------------------
// SuperLoss: tau = 0.9*0.5 + 0.1*mean(loss); z = max(-1/e+eps, (loss-tau)/2);
// sigma = exp(-W(z)) = W(z)/z; superloss = sigma*loss.
// Output layout: d_out[0:N] = superloss, d_out[N:2N] = sigma.
//
// R4 changes:
//  - K1: 4 independent accumulators + front-batched float4 loads (MLP_p1=4)
//  - tau finalization fused into K1 via last-block-done (K2 eliminated)
// ---------------------------------------------------------------------------

#define REDUCE_BLOCKS 2048
#define REDUCE_THREADS 256

__device__ float g_partials[REDUCE_BLOCKS];
__device__ unsigned int g_done_count = 0;
__device__ float g_tau;

// ----------------- K1: partial sums + last-block tau finalize --------------
__global__ void __launch_bounds__(REDUCE_THREADS)
sum_tau_kernel(const float* __restrict__ x, int n) {
    __shared__ float sdata[REDUCE_THREADS];
    __shared__ bool is_last;
    int tid = threadIdx.x;
    long long gid = (long long)blockIdx.x * REDUCE_THREADS + tid;
    long long stride = (long long)REDUCE_BLOCKS * REDUCE_THREADS;

    int n4 = n >> 2;
    const float4* x4 = (const float4*)x;

    // 4 independent accumulators, 4 front-batched loads per iteration
    float s0 = 0.0f, s1 = 0.0f, s2 = 0.0f, s3 = 0.0f;
    long long i = gid;
    for (; i + 3 * stride < n4; i += 4 * stride) {
        float4 a = __ldg(&x4[i]);
        float4 b = __ldg(&x4[i + stride]);
        float4 c = __ldg(&x4[i + 2 * stride]);
        float4 d = __ldg(&x4[i + 3 * stride]);
        s0 += (a.x + a.y) + (a.z + a.w);
        s1 += (b.x + b.y) + (b.z + b.w);
        s2 += (c.x + c.y) + (c.z + c.w);
        s3 += (d.x + d.y) + (d.z + d.w);
    }
    for (; i < n4; i += stride) {
        float4 a = __ldg(&x4[i]);
        s0 += (a.x + a.y) + (a.z + a.w);
    }
    // scalar tail (n not multiple of 4)
    for (long long j = (long long)(n4 << 2) + gid; j < n; j += stride)
        s0 += __ldg(&x[j]);

    sdata[tid] = (s0 + s1) + (s2 + s3);
    __syncthreads();
    #pragma unroll
    for (int off = REDUCE_THREADS / 2; off > 0; off >>= 1) {
        if (tid < off) sdata[tid] += sdata[tid + off];
        __syncthreads();
    }
    if (tid == 0) {
        g_partials[blockIdx.x] = sdata[0];
        __threadfence();
        unsigned int prev = atomicAdd(&g_done_count, 1u);
        is_last = (prev == (unsigned int)(gridDim.x - 1));
    }
    __syncthreads();

    if (is_last) {
        // This block arrives last: all partials are visible. Reduce in double.
        __shared__ double dd[REDUCE_THREADS];
        double s = 0.0;
        for (int k = tid; k < REDUCE_BLOCKS; k += REDUCE_THREADS)
            s += (double)g_partials[k];
        dd[tid] = s;
        __syncthreads();
        #pragma unroll
        for (int off = REDUCE_THREADS / 2; off > 0; off >>= 1) {
            if (tid < off) dd[tid] += dd[tid + off];
            __syncthreads();
        }
        if (tid == 0) {
            double mean = dd[0] / (double)n;
            g_tau = (float)(0.9 * 0.5 + 0.1 * mean);  // MOM=0.1, TAU0=0.5
            g_done_count = 0;  // reset for next launch/replay
        }
    }
}

// --------------------------- Lambert W core --------------------------------
// One Halley step with a single divide:
//   w' = w - 2 f (w+1) / (2 e^w (w+1)^2 - (w+2) f),  f = w e^w - z
__device__ __forceinline__ float halley1(float w, float z) {
    float ew  = __expf(w);
    float f   = fmaf(w, ew, -z);
    float wp1 = w + 1.0f;
    float num = 2.0f * f * wp1;
    float den = fmaf(2.0f * ew, wp1 * wp1, -(w + 2.0f) * f);
    return w - __fdividef(num, den);
}

__device__ __forceinline__ float lambertw_fast(float z) {
    if (__builtin_expect(z < -0.32f, 0)) {
        // Branch-point region: unreachable for loss in [0,1) with tau~0.5,
        // kept for robustness.
        float p = sqrtf(fmaxf(2.0f * fmaf(2.7182818284590452f, z, 1.0f), 0.0f));
        float w = -1.0f + p * (1.0f - 0.33333333333f * p);
        w = halley1(w, z);
        w = halley1(w, z);
        w = halley1(w, z);
        return w;
    }
    // Taylor init (degree 6, pure FMA): err <= ~8e-3 on [-0.28, 0.28]
    float w0 = fmaf(z, -10.8f,       5.20833333f);
    w0 = fmaf(z, w0, -2.66666667f);
    w0 = fmaf(z, w0,  1.5f);
    w0 = fmaf(z, w0, -1.0f);
    w0 = fmaf(z, w0,  1.0f);
    float w = z * w0;
    return halley1(w, z);      // cubic -> ~5e-7
}

__device__ __forceinline__ void superloss_elem(float x, float tau,
                                               float& sl, float& sig) {
    const float ZMIN = -0.36787944117144233f + 1.1920929e-07f; // -1/e + eps
    float z = fmaxf(ZMIN, 0.5f * (x - tau));   // LAM = 1
    float w = lambertw_fast(z);
    // sigma = exp(-w) = w/z (since z = w e^w); Taylor limit at z->0
    float sig_v = (fabsf(z) > 1e-30f) ? __fdividef(w, z) : (1.0f - w);
    sig = sig_v;
    sl  = sig_v * x;
}

// --------------------------- K3: elementwise -------------------------------
__global__ void __launch_bounds__(256)
superloss_kernel(const float* __restrict__ x,
                 float* __restrict__ out_sl,
                 float* __restrict__ out_sig,
                 int n) {
    float tau = g_tau;
    int n4 = n >> 2;
    long long i = (long long)blockIdx.x * blockDim.x + threadIdx.x;
    long long stride = (long long)gridDim.x * blockDim.x;

    const float4* x4 = (const float4*)x;
    float4* sl4 = (float4*)out_sl;
    float4* sg4 = (float4*)out_sig;

    for (; i < n4; i += stride) {
        float4 v = __ldg(&x4[i]);
        float4 sl, sg;
        superloss_elem(v.x, tau, sl.x, sg.x);
        superloss_elem(v.y, tau, sl.y, sg.y);
        superloss_elem(v.z, tau, sl.z, sg.z);
        superloss_elem(v.w, tau, sl.w, sg.w);
        __stcs(&sl4[i], sl);   // streaming stores: outputs never re-read
        __stcs(&sg4[i], sg);
    }
    long long base = (long long)n4 << 2;
    for (long long j = base + (long long)blockIdx.x * blockDim.x + threadIdx.x;
         j < n; j += stride) {
        float sl, sg;
        superloss_elem(__ldg(&x[j]), tau, sl, sg);
        out_sl[j] = sl;
        out_sig[j] = sg;
    }
}

// --------------------------- launcher --------------------------------------
extern "C" void kernel_launch(void* const* d_in, const int* in_sizes, int n_in,
                              void* d_out, int out_size) {
    const float* loss = (const float*)d_in[0];
    int n = in_sizes[0];
    float* out = (float*)d_out;
    float* out_sl  = out;
    float* out_sig = out + n;

    sum_tau_kernel<<<REDUCE_BLOCKS, REDUCE_THREADS>>>(loss, n);

    int n4 = n >> 2;
    int blocks = (n4 + 255) / 256;
    if (blocks > 16384) blocks = 16384;
    if (blocks < 1) blocks = 1;
    superloss_kernel<<<blocks, 256>>>(loss, out_sl, out_sig, n);
}

// round 5
// speedup vs baseline: 1.0072x; 1.0072x over previous
#include <cuda_runtime.h>
#include <cuda_bf16.h>
#include <math.h>

// ---------------------------------------------------------------------------
// SuperLoss: tau = 0.9*0.5 + 0.1*mean(loss); z = max(-1/e+eps, (loss-tau)/2);
// sigma = exp(-W(z)) = W(z)/z; superloss = sigma*loss.
// Output layout: d_out[0:N] = superloss, d_out[N:2N] = sigma.
//
// R4 changes:
//  - K1: 4 independent accumulators + front-batched float4 loads (MLP_p1=4)
//  - tau finalization fused into K1 via last-block-done (K2 eliminated)
// ---------------------------------------------------------------------------

#define REDUCE_BLOCKS 2048
#define REDUCE_THREADS 256

__device__ float g_partials[REDUCE_BLOCKS];
__device__ unsigned int g_done_count = 0;
__device__ float g_tau;

// ----------------- K1: partial sums + last-block tau finalize --------------
__global__ void __launch_bounds__(REDUCE_THREADS)
sum_tau_kernel(const float* __restrict__ x, int n) {
    __shared__ float sdata[REDUCE_THREADS];
    __shared__ bool is_last;
    int tid = threadIdx.x;
    long long gid = (long long)blockIdx.x * REDUCE_THREADS + tid;
    long long stride = (long long)REDUCE_BLOCKS * REDUCE_THREADS;

    int n4 = n >> 2;
    const float4* x4 = (const float4*)x;

    // 4 independent accumulators, 4 front-batched loads per iteration
    float s0 = 0.0f, s1 = 0.0f, s2 = 0.0f, s3 = 0.0f;
    long long i = gid;
    for (; i + 3 * stride < n4; i += 4 * stride) {
        float4 a = __ldg(&x4[i]);
        float4 b = __ldg(&x4[i + stride]);
        float4 c = __ldg(&x4[i + 2 * stride]);
        float4 d = __ldg(&x4[i + 3 * stride]);
        s0 += (a.x + a.y) + (a.z + a.w);
        s1 += (b.x + b.y) + (b.z + b.w);
        s2 += (c.x + c.y) + (c.z + c.w);
        s3 += (d.x + d.y) + (d.z + d.w);
    }
    for (; i < n4; i += stride) {
        float4 a = __ldg(&x4[i]);
        s0 += (a.x + a.y) + (a.z + a.w);
    }
    // scalar tail (n not multiple of 4)
    for (long long j = (long long)(n4 << 2) + gid; j < n; j += stride)
        s0 += __ldg(&x[j]);

    sdata[tid] = (s0 + s1) + (s2 + s3);
    __syncthreads();
    #pragma unroll
    for (int off = REDUCE_THREADS / 2; off > 0; off >>= 1) {
        if (tid < off) sdata[tid] += sdata[tid + off];
        __syncthreads();
    }
    if (tid == 0) {
        g_partials[blockIdx.x] = sdata[0];
        __threadfence();
        unsigned int prev = atomicAdd(&g_done_count, 1u);
        is_last = (prev == (unsigned int)(gridDim.x - 1));
    }
    __syncthreads();

    if (is_last) {
        // This block arrives last: all partials are visible. Reduce in double.
        __shared__ double dd[REDUCE_THREADS];
        double s = 0.0;
        for (int k = tid; k < REDUCE_BLOCKS; k += REDUCE_THREADS)
            s += (double)g_partials[k];
        dd[tid] = s;
        __syncthreads();
        #pragma unroll
        for (int off = REDUCE_THREADS / 2; off > 0; off >>= 1) {
            if (tid < off) dd[tid] += dd[tid + off];
            __syncthreads();
        }
        if (tid == 0) {
            double mean = dd[0] / (double)n;
            g_tau = (float)(0.9 * 0.5 + 0.1 * mean);  // MOM=0.1, TAU0=0.5
            g_done_count = 0;  // reset for next launch/replay
        }
    }
}

// --------------------------- Lambert W core --------------------------------
// One Halley step with a single divide:
//   w' = w - 2 f (w+1) / (2 e^w (w+1)^2 - (w+2) f),  f = w e^w - z
__device__ __forceinline__ float halley1(float w, float z) {
    float ew  = __expf(w);
    float f   = fmaf(w, ew, -z);
    float wp1 = w + 1.0f;
    float num = 2.0f * f * wp1;
    float den = fmaf(2.0f * ew, wp1 * wp1, -(w + 2.0f) * f);
    return w - __fdividef(num, den);
}

__device__ __forceinline__ float lambertw_fast(float z) {
    if (__builtin_expect(z < -0.32f, 0)) {
        // Branch-point region: unreachable for loss in [0,1) with tau~0.5,
        // kept for robustness.
        float p = sqrtf(fmaxf(2.0f * fmaf(2.7182818284590452f, z, 1.0f), 0.0f));
        float w = -1.0f + p * (1.0f - 0.33333333333f * p);
        w = halley1(w, z);
        w = halley1(w, z);
        w = halley1(w, z);
        return w;
    }
    // Taylor init (degree 6, pure FMA): err <= ~8e-3 on [-0.28, 0.28]
    float w0 = fmaf(z, -10.8f,       5.20833333f);
    w0 = fmaf(z, w0, -2.66666667f);
    w0 = fmaf(z, w0,  1.5f);
    w0 = fmaf(z, w0, -1.0f);
    w0 = fmaf(z, w0,  1.0f);
    float w = z * w0;
    return halley1(w, z);      // cubic -> ~5e-7
}

__device__ __forceinline__ void superloss_elem(float x, float tau,
                                               float& sl, float& sig) {
    const float ZMIN = -0.36787944117144233f + 1.1920929e-07f; // -1/e + eps
    float z = fmaxf(ZMIN, 0.5f * (x - tau));   // LAM = 1
    float w = lambertw_fast(z);
    // sigma = exp(-w) = w/z (since z = w e^w); Taylor limit at z->0
    float sig_v = (fabsf(z) > 1e-30f) ? __fdividef(w, z) : (1.0f - w);
    sig = sig_v;
    sl  = sig_v * x;
}

// --------------------------- K3: elementwise -------------------------------
__global__ void __launch_bounds__(256)
superloss_kernel(const float* __restrict__ x,
                 float* __restrict__ out_sl,
                 float* __restrict__ out_sig,
                 int n) {
    float tau = g_tau;
    int n4 = n >> 2;
    long long i = (long long)blockIdx.x * blockDim.x + threadIdx.x;
    long long stride = (long long)gridDim.x * blockDim.x;

    const float4* x4 = (const float4*)x;
    float4* sl4 = (float4*)out_sl;
    float4* sg4 = (float4*)out_sig;

    for (; i < n4; i += stride) {
        float4 v = __ldg(&x4[i]);
        float4 sl, sg;
        superloss_elem(v.x, tau, sl.x, sg.x);
        superloss_elem(v.y, tau, sl.y, sg.y);
        superloss_elem(v.z, tau, sl.z, sg.z);
        superloss_elem(v.w, tau, sl.w, sg.w);
        __stcs(&sl4[i], sl);   // streaming stores: outputs never re-read
        __stcs(&sg4[i], sg);
    }
    long long base = (long long)n4 << 2;
    for (long long j = base + (long long)blockIdx.x * blockDim.x + threadIdx.x;
         j < n; j += stride) {
        float sl, sg;
        superloss_elem(__ldg(&x[j]), tau, sl, sg);
        out_sl[j] = sl;
        out_sig[j] = sg;
    }
}

// --------------------------- launcher --------------------------------------
extern "C" void kernel_launch(void* const* d_in, const int* in_sizes, int n_in,
                              void* d_out, int out_size) {
    const float* loss = (const float*)d_in[0];
    int n = in_sizes[0];
    float* out = (float*)d_out;
    float* out_sl  = out;
    float* out_sig = out + n;

    sum_tau_kernel<<<REDUCE_BLOCKS, REDUCE_THREADS>>>(loss, n);

    int n4 = n >> 2;
    int blocks = (n4 + 255) / 256;
    if (blocks > 16384) blocks = 16384;
    if (blocks < 1) blocks = 1;
    superloss_kernel<<<blocks, 256>>>(loss, out_sl, out_sig, n);
}

// round 6
// speedup vs baseline: 1.0763x; 1.0686x over previous
#include <cuda_runtime.h>
#include <cuda_bf16.h>
#include <math.h>

// ---------------------------------------------------------------------------
// SuperLoss: tau = 0.9*0.5 + 0.1*mean(loss); z = max(-1/e+eps, (loss-tau)/2);
// sigma = exp(-W(z)); superloss = sigma*loss.
// Output: d_out[0:N] = superloss, d_out[N:2N] = sigma.
//
// R6: sigma(z) = exp(-W(z)) evaluated as a degree-14 Taylor polynomial
// (coeffs c_k = (-1)^k (k+1)^k/(k+1)!), valid since z in (-0.25,0.25) here.
// 14 FMA, zero MUFU, zero branches on the hot path -> K3 becomes write-bound.
// Cold exp/Halley fallback kept for |z| > 0.26.
// ---------------------------------------------------------------------------

#define REDUCE_BLOCKS 2048
#define REDUCE_THREADS 256

__device__ float g_partials[REDUCE_BLOCKS];
__device__ unsigned int g_done_count = 0;
__device__ float g_tau;

// ----------------- K1: partial sums + last-block tau finalize --------------
__global__ void __launch_bounds__(REDUCE_THREADS)
sum_tau_kernel(const float* __restrict__ x, int n) {
    __shared__ float sdata[REDUCE_THREADS];
    __shared__ bool is_last;
    int tid = threadIdx.x;
    long long gid = (long long)blockIdx.x * REDUCE_THREADS + tid;
    long long stride = (long long)REDUCE_BLOCKS * REDUCE_THREADS;

    int n4 = n >> 2;
    const float4* x4 = (const float4*)x;

    // 8 independent accumulators, 8 front-batched float4 loads (MLP_p1=8).
    // For N=16.7M this loop body executes exactly once per thread.
    float s0 = 0.f, s1 = 0.f, s2 = 0.f, s3 = 0.f;
    float s4 = 0.f, s5 = 0.f, s6 = 0.f, s7 = 0.f;
    long long i = gid;
    for (; i + 7 * stride < n4; i += 8 * stride) {
        float4 a = __ldg(&x4[i]);
        float4 b = __ldg(&x4[i + stride]);
        float4 c = __ldg(&x4[i + 2 * stride]);
        float4 d = __ldg(&x4[i + 3 * stride]);
        float4 e = __ldg(&x4[i + 4 * stride]);
        float4 f = __ldg(&x4[i + 5 * stride]);
        float4 g = __ldg(&x4[i + 6 * stride]);
        float4 h = __ldg(&x4[i + 7 * stride]);
        s0 += (a.x + a.y) + (a.z + a.w);
        s1 += (b.x + b.y) + (b.z + b.w);
        s2 += (c.x + c.y) + (c.z + c.w);
        s3 += (d.x + d.y) + (d.z + d.w);
        s4 += (e.x + e.y) + (e.z + e.w);
        s5 += (f.x + f.y) + (f.z + f.w);
        s6 += (g.x + g.y) + (g.z + g.w);
        s7 += (h.x + h.y) + (h.z + h.w);
    }
    for (; i < n4; i += stride) {
        float4 a = __ldg(&x4[i]);
        s0 += (a.x + a.y) + (a.z + a.w);
    }
    for (long long j = (long long)(n4 << 2) + gid; j < n; j += stride)
        s0 += __ldg(&x[j]);

    sdata[tid] = ((s0 + s1) + (s2 + s3)) + ((s4 + s5) + (s6 + s7));
    __syncthreads();
    #pragma unroll
    for (int off = REDUCE_THREADS / 2; off > 0; off >>= 1) {
        if (tid < off) sdata[tid] += sdata[tid + off];
        __syncthreads();
    }
    if (tid == 0) {
        g_partials[blockIdx.x] = sdata[0];
        __threadfence();
        unsigned int prev = atomicAdd(&g_done_count, 1u);
        is_last = (prev == (unsigned int)(gridDim.x - 1));
    }
    __syncthreads();

    if (is_last) {
        __shared__ double dd[REDUCE_THREADS];
        double s = 0.0;
        for (int k = tid; k < REDUCE_BLOCKS; k += REDUCE_THREADS)
            s += (double)g_partials[k];
        dd[tid] = s;
        __syncthreads();
        #pragma unroll
        for (int off = REDUCE_THREADS / 2; off > 0; off >>= 1) {
            if (tid < off) dd[tid] += dd[tid + off];
            __syncthreads();
        }
        if (tid == 0) {
            double mean = dd[0] / (double)n;
            g_tau = (float)(0.9 * 0.5 + 0.1 * mean);  // MOM=0.1, TAU0=0.5
            g_done_count = 0;  // reset for graph replay
        }
    }
}

// ------------------- cold fallback: exp/Halley Lambert W -------------------
__device__ __forceinline__ float halley1(float w, float z) {
    float ew  = __expf(w);
    float f   = fmaf(w, ew, -z);
    float wp1 = w + 1.0f;
    float num = 2.0f * f * wp1;
    float den = fmaf(2.0f * ew, wp1 * wp1, -(w + 2.0f) * f);
    return w - __fdividef(num, den);
}

__device__ __noinline__ float sigma_slow(float z) {
    float w;
    if (z < -0.32f) {  // near branch point
        float p = sqrtf(fmaxf(2.0f * fmaf(2.7182818284590452f, z, 1.0f), 0.0f));
        w = -1.0f + p * (1.0f - 0.33333333333f * p);
    } else {
        w = __logf(1.0f + z);
    }
    w = halley1(w, z);
    w = halley1(w, z);
    w = halley1(w, z);
    return (fabsf(z) > 1e-30f) ? __fdividef(w, z) : (1.0f - w);
}

// ----------------- hot path: sigma(z) as degree-14 Taylor ------------------
// sigma(z) = sum_k c_k z^k, c_k = (-1)^k (k+1)^k / (k+1)!
__device__ __forceinline__ float sigma_poly(float z) {
    float s =            22324.301f;    // c14
    s = fmaf(s, z,      -9104.5002f);   // c13
    s = fmaf(s, z,       3741.4497f);   // c12
    s = fmaf(s, z,      -1551.1605f);   // c11
    s = fmaf(s, z,        649.78717f);  // c10
    s = fmaf(s, z,       -275.57319f);  // c9
    s = fmaf(s, z,        118.62522f);  // c8
    s = fmaf(s, z,        -52.012698f); // c7
    s = fmaf(s, z,         23.343056f); // c6
    s = fmaf(s, z,        -10.8f);      // c5
    s = fmaf(s, z,          5.2083333f);// c4
    s = fmaf(s, z,         -2.6666667f);// c3
    s = fmaf(s, z,          1.5f);      // c2
    s = fmaf(s, z,         -1.0f);      // c1
    s = fmaf(s, z,          1.0f);      // c0
    return s;
}

__device__ __forceinline__ void superloss_elem(float x, float half_tau,
                                               float& sl, float& sig) {
    const float ZMIN = -0.36787944117144233f + 1.1920929e-07f; // -1/e + eps
    float z = fmaxf(ZMIN, fmaf(0.5f, x, -half_tau));  // LAM=1
    float s;
    if (__builtin_expect(fabsf(z) > 0.26f, 0))
        s = sigma_slow(z);       // cold: outside the fitted interval
    else
        s = sigma_poly(z);       // hot: pure FMA
    sig = s;
    sl  = s * x;
}

// --------------------------- K3: elementwise -------------------------------
__global__ void __launch_bounds__(256)
superloss_kernel(const float* __restrict__ x,
                 float* __restrict__ out_sl,
                 float* __restrict__ out_sig,
                 int n) {
    float half_tau = 0.5f * g_tau;
    int n4 = n >> 2;
    long long i = (long long)blockIdx.x * blockDim.x + threadIdx.x;
    long long stride = (long long)gridDim.x * blockDim.x;

    const float4* x4 = (const float4*)x;
    float4* sl4 = (float4*)out_sl;
    float4* sg4 = (float4*)out_sig;

    for (; i < n4; i += stride) {
        float4 v = __ldg(&x4[i]);
        float4 sl, sg;
        superloss_elem(v.x, half_tau, sl.x, sg.x);
        superloss_elem(v.y, half_tau, sl.y, sg.y);
        superloss_elem(v.z, half_tau, sl.z, sg.z);
        superloss_elem(v.w, half_tau, sl.w, sg.w);
        __stcs(&sl4[i], sl);   // streaming stores: never re-read
        __stcs(&sg4[i], sg);
    }
    long long base = (long long)n4 << 2;
    for (long long j = base + (long long)blockIdx.x * blockDim.x + threadIdx.x;
         j < n; j += stride) {
        float sl, sg;
        superloss_elem(__ldg(&x[j]), half_tau, sl, sg);
        out_sl[j] = sl;
        out_sig[j] = sg;
    }
}

// --------------------------- launcher --------------------------------------
extern "C" void kernel_launch(void* const* d_in, const int* in_sizes, int n_in,
                              void* d_out, int out_size) {
    const float* loss = (const float*)d_in[0];
    int n = in_sizes[0];
    float* out = (float*)d_out;
    float* out_sl  = out;
    float* out_sig = out + n;

    sum_tau_kernel<<<REDUCE_BLOCKS, REDUCE_THREADS>>>(loss, n);

    int n4 = n >> 2;
    int blocks = (n4 + 255) / 256;
    if (blocks > 16384) blocks = 16384;
    if (blocks < 1) blocks = 1;
    superloss_kernel<<<blocks, 256>>>(loss, out_sl, out_sig, n);
}

// round 7
// speedup vs baseline: 1.0938x; 1.0163x over previous
#include <cuda_runtime.h>
#include <cuda_bf16.h>
#include <math.h>

// ---------------------------------------------------------------------------
// SuperLoss: tau = 0.9*0.5 + 0.1*mean(loss); z = max(-1/e+eps, (loss-tau)/2);
// sigma = exp(-W(z)); superloss = sigma*loss.
// Output: d_out[0:N] = superloss, d_out[N:2N] = sigma.
//
// R7:
//  - K3: exact grid, 1 float4/thread, int32 indexing, no loops, 1 guard/quad
//  - K1: single-wave grid (1184 = 148 SM x 8 resident blocks)
// ---------------------------------------------------------------------------

#define REDUCE_BLOCKS 1184          // 148 SMs x 8 blocks -> exactly one wave
#define REDUCE_THREADS 256

__device__ float g_partials[REDUCE_BLOCKS];
__device__ unsigned int g_done_count = 0;
__device__ float g_tau;

// ----------------- K1: partial sums + last-block tau finalize --------------
__global__ void __launch_bounds__(REDUCE_THREADS, 8)
sum_tau_kernel(const float* __restrict__ x, int n) {
    __shared__ float sdata[REDUCE_THREADS];
    __shared__ bool is_last;
    int tid = threadIdx.x;
    int gid = blockIdx.x * REDUCE_THREADS + tid;
    const int stride = REDUCE_BLOCKS * REDUCE_THREADS;

    int n4 = n >> 2;
    const float4* x4 = (const float4*)x;

    // 8 independent accumulators, 8 front-batched float4 loads (MLP_p1=8)
    float s0 = 0.f, s1 = 0.f, s2 = 0.f, s3 = 0.f;
    float s4 = 0.f, s5 = 0.f, s6 = 0.f, s7 = 0.f;
    int i = gid;
    for (; i + 7 * stride < n4; i += 8 * stride) {
        float4 a = __ldg(&x4[i]);
        float4 b = __ldg(&x4[i + stride]);
        float4 c = __ldg(&x4[i + 2 * stride]);
        float4 d = __ldg(&x4[i + 3 * stride]);
        float4 e = __ldg(&x4[i + 4 * stride]);
        float4 f = __ldg(&x4[i + 5 * stride]);
        float4 g = __ldg(&x4[i + 6 * stride]);
        float4 h = __ldg(&x4[i + 7 * stride]);
        s0 += (a.x + a.y) + (a.z + a.w);
        s1 += (b.x + b.y) + (b.z + b.w);
        s2 += (c.x + c.y) + (c.z + c.w);
        s3 += (d.x + d.y) + (d.z + d.w);
        s4 += (e.x + e.y) + (e.z + e.w);
        s5 += (f.x + f.y) + (f.z + f.w);
        s6 += (g.x + g.y) + (g.z + g.w);
        s7 += (h.x + h.y) + (h.z + h.w);
    }
    for (; i < n4; i += stride) {
        float4 a = __ldg(&x4[i]);
        s0 += (a.x + a.y) + (a.z + a.w);
    }
    for (int j = (n4 << 2) + gid; j < n; j += stride)
        s0 += __ldg(&x[j]);

    sdata[tid] = ((s0 + s1) + (s2 + s3)) + ((s4 + s5) + (s6 + s7));
    __syncthreads();
    #pragma unroll
    for (int off = REDUCE_THREADS / 2; off > 0; off >>= 1) {
        if (tid < off) sdata[tid] += sdata[tid + off];
        __syncthreads();
    }
    if (tid == 0) {
        g_partials[blockIdx.x] = sdata[0];
        __threadfence();
        unsigned int prev = atomicAdd(&g_done_count, 1u);
        is_last = (prev == (unsigned int)(gridDim.x - 1));
    }
    __syncthreads();

    if (is_last) {
        __shared__ double dd[REDUCE_THREADS];
        double s = 0.0;
        for (int k = tid; k < REDUCE_BLOCKS; k += REDUCE_THREADS)
            s += (double)g_partials[k];
        dd[tid] = s;
        __syncthreads();
        #pragma unroll
        for (int off = REDUCE_THREADS / 2; off > 0; off >>= 1) {
            if (tid < off) dd[tid] += dd[tid + off];
            __syncthreads();
        }
        if (tid == 0) {
            double mean = dd[0] / (double)n;
            g_tau = (float)(0.9 * 0.5 + 0.1 * mean);  // MOM=0.1, TAU0=0.5
            g_done_count = 0;  // reset for graph replay
        }
    }
}

// ------------------- cold fallback: exp/Halley Lambert W -------------------
__device__ __forceinline__ float halley1(float w, float z) {
    float ew  = __expf(w);
    float f   = fmaf(w, ew, -z);
    float wp1 = w + 1.0f;
    float num = 2.0f * f * wp1;
    float den = fmaf(2.0f * ew, wp1 * wp1, -(w + 2.0f) * f);
    return w - __fdividef(num, den);
}

__device__ __noinline__ float sigma_slow(float z) {
    float w;
    if (z < -0.32f) {
        float p = sqrtf(fmaxf(2.0f * fmaf(2.7182818284590452f, z, 1.0f), 0.0f));
        w = -1.0f + p * (1.0f - 0.33333333333f * p);
    } else {
        w = __logf(1.0f + z);
    }
    w = halley1(w, z);
    w = halley1(w, z);
    w = halley1(w, z);
    return (fabsf(z) > 1e-30f) ? __fdividef(w, z) : (1.0f - w);
}

// ----------------- hot path: sigma(z) as degree-14 Taylor ------------------
// sigma(z) = exp(-W(z)) = sum_k c_k z^k, c_k = (-1)^k (k+1)^k / (k+1)!
__device__ __forceinline__ float sigma_poly(float z) {
    float s =            22324.301f;    // c14
    s = fmaf(s, z,      -9104.5002f);   // c13
    s = fmaf(s, z,       3741.4497f);   // c12
    s = fmaf(s, z,      -1551.1605f);   // c11
    s = fmaf(s, z,        649.78717f);  // c10
    s = fmaf(s, z,       -275.57319f);  // c9
    s = fmaf(s, z,        118.62522f);  // c8
    s = fmaf(s, z,        -52.012698f); // c7
    s = fmaf(s, z,         23.343056f); // c6
    s = fmaf(s, z,        -10.8f);      // c5
    s = fmaf(s, z,          5.2083333f);// c4
    s = fmaf(s, z,         -2.6666667f);// c3
    s = fmaf(s, z,          1.5f);      // c2
    s = fmaf(s, z,         -1.0f);      // c1
    s = fmaf(s, z,          1.0f);      // c0
    return s;
}

// --------------------------- K3: elementwise -------------------------------
// Exact grid: thread t < n4 handles float4 t; threads [n4, n4+tail) handle
// the scalar tail. No loops, int32 indexing only.
__global__ void __launch_bounds__(256)
superloss_kernel(const float* __restrict__ x,
                 float* __restrict__ out_sl,
                 float* __restrict__ out_sig,
                 int n4, int n_tail) {
    const float ZMIN = -0.36787944117144233f + 1.1920929e-07f; // -1/e + eps
    float half_tau = 0.5f * g_tau;
    int t = blockIdx.x * 256 + threadIdx.x;

    if (t < n4) {
        const float4* x4 = (const float4*)x;
        float4 v = __ldg(&x4[t]);

        float z0 = fmaxf(ZMIN, fmaf(0.5f, v.x, -half_tau));
        float z1 = fmaxf(ZMIN, fmaf(0.5f, v.y, -half_tau));
        float z2 = fmaxf(ZMIN, fmaf(0.5f, v.z, -half_tau));
        float z3 = fmaxf(ZMIN, fmaf(0.5f, v.w, -half_tau));

        float4 sg, sl;
        float m = fmaxf(fmaxf(fabsf(z0), fabsf(z1)),
                        fmaxf(fabsf(z2), fabsf(z3)));
        if (__builtin_expect(m > 0.26f, 0)) {       // cold: never taken here
            sg.x = sigma_slow(z0);
            sg.y = sigma_slow(z1);
            sg.z = sigma_slow(z2);
            sg.w = sigma_slow(z3);
        } else {                                    // hot: pure FMA
            sg.x = sigma_poly(z0);
            sg.y = sigma_poly(z1);
            sg.z = sigma_poly(z2);
            sg.w = sigma_poly(z3);
        }
        sl.x = sg.x * v.x;
        sl.y = sg.y * v.y;
        sl.z = sg.z * v.z;
        sl.w = sg.w * v.w;

        __stcs(&((float4*)out_sl)[t], sl);   // streaming: never re-read
        __stcs(&((float4*)out_sig)[t], sg);
    } else {
        int r = t - n4;
        if (r < n_tail) {
            int j = (n4 << 2) + r;
            float xv = __ldg(&x[j]);
            float z = fmaxf(ZMIN, fmaf(0.5f, xv, -half_tau));
            float s = (fabsf(z) > 0.26f) ? sigma_slow(z) : sigma_poly(z);
            out_sl[j]  = s * xv;
            out_sig[j] = s;
        }
    }
}

// --------------------------- launcher --------------------------------------
extern "C" void kernel_launch(void* const* d_in, const int* in_sizes, int n_in,
                              void* d_out, int out_size) {
    const float* loss = (const float*)d_in[0];
    int n = in_sizes[0];
    float* out = (float*)d_out;
    float* out_sl  = out;
    float* out_sig = out + n;

    sum_tau_kernel<<<REDUCE_BLOCKS, REDUCE_THREADS>>>(loss, n);

    int n4 = n >> 2;
    int n_tail = n - (n4 << 2);
    int work = n4 + n_tail;               // one thread per quad + tail threads
    int blocks = (work + 255) / 256;
    if (blocks < 1) blocks = 1;
    superloss_kernel<<<blocks, 256>>>(loss, out_sl, out_sig, n4, n_tail);
}